// round 1
// baseline (speedup 1.0000x reference)
#include <cuda_runtime.h>
#include <math.h>

// Problem constants
#define Bb   8
#define Tt   2048
#define Dd   1024
#define Hh   8
#define Cc   64
#define DVv  128
#define Mm   (Bb*Tt)        // 16384 token rows
#define NPROJ 704           // q(64) | k(64) | v(64) | alpha(512)

// ---------------- scratch (device globals; no allocation allowed) ----------
__device__ float g_xn  [(size_t)Mm*Dd];      // 64 MB  layernormed x
__device__ float g_wall[(size_t)NPROJ*Dd];   // 2.8 MB concat(Wq,Wk,Wv,Wa)
__device__ float g_proj[(size_t)Mm*NPROJ];   // 44 MB  q_lat|kn|v_lat|alpha
__device__ float g_q   [(size_t)Bb*Hh*Tt*Cc];   // 32 MB  rotated q (b,h,t,c)
__device__ float g_v   [(size_t)Bb*Hh*Tt*DVv];  // 64 MB  up-proj v (b,h,t,d)
__device__ float g_o   [(size_t)Mm*Dd];      // 64 MB  attn out (b,t,h*dv)

// ---------------- 1. LayerNorm -------------------------------------------
__global__ __launch_bounds__(256)
void ln_kernel(const float* __restrict__ x, const float* __restrict__ gamma,
               const float* __restrict__ beta)
{
    int row = blockIdx.x;
    int tid = threadIdx.x;
    const float4* xr = (const float4*)(x + (size_t)row*Dd);
    float4 v = xr[tid];
    float s  = v.x + v.y + v.z + v.w;
    float s2 = v.x*v.x + v.y*v.y + v.z*v.z + v.w*v.w;
    #pragma unroll
    for (int o = 16; o > 0; o >>= 1) {
        s  += __shfl_xor_sync(0xffffffffu, s,  o);
        s2 += __shfl_xor_sync(0xffffffffu, s2, o);
    }
    __shared__ float r1[8], r2[8];
    int w = tid >> 5, l = tid & 31;
    if (l == 0) { r1[w] = s; r2[w] = s2; }
    __syncthreads();
    s = 0.f; s2 = 0.f;
    #pragma unroll
    for (int i = 0; i < 8; i++) { s += r1[i]; s2 += r2[i]; }
    float mu  = s * (1.f/Dd);
    float var = s2 * (1.f/Dd) - mu*mu;
    float inv = rsqrtf(var + 1e-5f);
    float4 g  = ((const float4*)gamma)[tid];
    float4 be = ((const float4*)beta)[tid];
    float4 o;
    o.x = (v.x - mu)*inv*g.x + be.x;
    o.y = (v.y - mu)*inv*g.y + be.y;
    o.z = (v.z - mu)*inv*g.z + be.z;
    o.w = (v.w - mu)*inv*g.w + be.w;
    ((float4*)(g_xn + (size_t)row*Dd))[tid] = o;
}

// ---------------- 2. concat weights (Wq|Wk|Wv|Wa) -------------------------
__global__ void build_wall(const float* __restrict__ Wq, const float* __restrict__ Wk,
                           const float* __restrict__ Wv, const float* __restrict__ Wa)
{
    int i = blockIdx.x * blockDim.x + threadIdx.x;   // 0 .. 704*1024-1
    int row = i >> 10, col = i & 1023;
    float val;
    if      (row <  64) val = Wq[(size_t)row       *1024 + col];
    else if (row < 128) val = Wk[(size_t)(row- 64) *1024 + col];
    else if (row < 192) val = Wv[(size_t)(row-128) *1024 + col];
    else                val = Wa[(size_t)(row-192) *1024 + col];
    g_wall[i] = val;
}

// ---------------- 3. generic SGEMM  Y[M,N] = A[M,K] @ W[N,K]^T (+resid) ---
__global__ __launch_bounds__(256)
void sgemm_nt(int M, int N, int K,
              const float* __restrict__ A,
              const float* __restrict__ W,
              float* __restrict__ Y,
              const float* __restrict__ resid)
{
    __shared__ float As[8][128];
    __shared__ float Ws[8][128];
    int tid  = threadIdx.x;
    int row0 = blockIdx.y * 128;
    int col0 = blockIdx.x * 128;
    int tx = tid & 15, ty = tid >> 4;
    int lm = tid >> 1;
    int lk = (tid & 1) * 4;
    const float* Ap = A + (size_t)(row0 + lm) * K + lk;
    const float* Wp = W + (size_t)(col0 + lm) * K + lk;
    bool wok = (col0 + lm) < N;
    float acc[8][8];
    #pragma unroll
    for (int i = 0; i < 8; i++)
        #pragma unroll
        for (int j = 0; j < 8; j++) acc[i][j] = 0.f;

    for (int k0 = 0; k0 < K; k0 += 8) {
        float4 a4 = *(const float4*)(Ap + k0);
        float4 w4 = wok ? *(const float4*)(Wp + k0) : make_float4(0.f,0.f,0.f,0.f);
        __syncthreads();
        As[lk+0][lm] = a4.x; As[lk+1][lm] = a4.y; As[lk+2][lm] = a4.z; As[lk+3][lm] = a4.w;
        Ws[lk+0][lm] = w4.x; Ws[lk+1][lm] = w4.y; Ws[lk+2][lm] = w4.z; Ws[lk+3][lm] = w4.w;
        __syncthreads();
        #pragma unroll
        for (int k = 0; k < 8; k++) {
            float af[8], wf[8];
            *(float4*)(af)   = *(const float4*)&As[k][ty*8];
            *(float4*)(af+4) = *(const float4*)&As[k][ty*8+4];
            *(float4*)(wf)   = *(const float4*)&Ws[k][tx*8];
            *(float4*)(wf+4) = *(const float4*)&Ws[k][tx*8+4];
            #pragma unroll
            for (int i = 0; i < 8; i++)
                #pragma unroll
                for (int j = 0; j < 8; j++)
                    acc[i][j] = fmaf(af[i], wf[j], acc[i][j]);
        }
    }
    #pragma unroll
    for (int i = 0; i < 8; i++) {
        int r = row0 + ty*8 + i;
        #pragma unroll
        for (int j = 0; j < 8; j++) {
            int c = col0 + tx*8 + j;
            if (c < N) {
                float val = acc[i][j];
                if (resid) val += resid[(size_t)r*N + c];
                Y[(size_t)r*N + c] = val;
            }
        }
    }
}

// ---------------- 4. epilogue: normalize k, sigmoid(alpha + bias) ---------
__global__ __launch_bounds__(128)
void epi_kernel(const float* __restrict__ Wa_b)
{
    int row = blockIdx.x;
    float* p = g_proj + (size_t)row * NPROJ;
    int tid = threadIdx.x;
    float kv = 0.f, sq = 0.f;
    if (tid < 64) { kv = p[64 + tid]; sq = kv * kv; }
    #pragma unroll
    for (int o = 16; o > 0; o >>= 1) sq += __shfl_xor_sync(0xffffffffu, sq, o);
    __shared__ float part[2];
    if ((tid & 31) == 0 && tid < 64) part[tid >> 5] = sq;
    __syncthreads();
    float inv = 1.f / fmaxf(sqrtf(part[0] + part[1]), 1e-12f);
    if (tid < 64) p[64 + tid] = kv * inv;
    #pragma unroll
    for (int r = 0; r < 4; r++) {
        int j = tid + r * 128;
        float a = p[192 + j] + Wa_b[j];
        p[192 + j] = 1.f / (1.f + expf(-a));
    }
}

// ---------------- 5. per-head transforms: q = qlat@Qc[h], v = vlat@Vc[h] --
__global__ __launch_bounds__(256)
void head_kernel(const float* __restrict__ Qc, const float* __restrict__ Vc)
{
    __shared__ float sX[Cc * 65];   // [c][t], padded
    __shared__ float sW[Cc * 64];   // [c][e] 64-wide weight tile
    int h    = blockIdx.y;
    int row0 = blockIdx.x * 64;
    int tid  = threadIdx.x;
    int bh   = (row0 >> 11) * Hh + h;
    int tt   = tid >> 2;
    int eb   = (tid & 3) * 16;
    int tg   = (row0 + tt) & (Tt - 1);

    // --- Q phase: sX <- q_lat tile (cols 0..63), sW <- Qc[h] ---
    #pragma unroll
    for (int it = 0; it < 4; it++) {
        int i = tid + it * 256;
        int t = i >> 4, c4 = (i & 15) * 4;
        float4 xv = *(const float4*)(g_proj + (size_t)(row0 + t) * NPROJ + c4);
        sX[(c4+0)*65 + t] = xv.x; sX[(c4+1)*65 + t] = xv.y;
        sX[(c4+2)*65 + t] = xv.z; sX[(c4+3)*65 + t] = xv.w;
    }
    {
        const float4* src = (const float4*)(Qc + (size_t)h * Cc * Cc);
        float4* dst = (float4*)sW;
        #pragma unroll
        for (int it = 0; it < 4; it++) dst[tid + it*256] = src[tid + it*256];
    }
    __syncthreads();
    {
        float acc[16];
        #pragma unroll
        for (int i = 0; i < 16; i++) acc[i] = 0.f;
        #pragma unroll
        for (int c = 0; c < 64; c++) {
            float xv = sX[c*65 + tt];
            const float* wr = sW + c*64 + eb;
            #pragma unroll
            for (int i = 0; i < 16; i++) acc[i] = fmaf(xv, wr[i], acc[i]);
        }
        float* outp = g_q + ((size_t)bh * Tt + tg) * Cc + eb;
        #pragma unroll
        for (int i = 0; i < 16; i += 4)
            *(float4*)(outp + i) = make_float4(acc[i], acc[i+1], acc[i+2], acc[i+3]);
    }
    __syncthreads();

    // --- V phase: sX <- v_lat tile (cols 128..191) ---
    #pragma unroll
    for (int it = 0; it < 4; it++) {
        int i = tid + it * 256;
        int t = i >> 4, c4 = (i & 15) * 4;
        float4 xv = *(const float4*)(g_proj + (size_t)(row0 + t) * NPROJ + 128 + c4);
        sX[(c4+0)*65 + t] = xv.x; sX[(c4+1)*65 + t] = xv.y;
        sX[(c4+2)*65 + t] = xv.z; sX[(c4+3)*65 + t] = xv.w;
    }
    for (int half = 0; half < 2; half++) {
        // sW <- Vc[h][:, half*64 : half*64+64]
        #pragma unroll
        for (int it = 0; it < 4; it++) {
            int i = tid + it * 256;
            int c = i >> 4, e4 = (i & 15) * 4;
            float4 wv = *(const float4*)(Vc + (size_t)h*Cc*DVv + (size_t)c*DVv + half*64 + e4);
            *(float4*)(sW + c*64 + e4) = wv;
        }
        __syncthreads();
        float acc[16];
        #pragma unroll
        for (int i = 0; i < 16; i++) acc[i] = 0.f;
        #pragma unroll
        for (int c = 0; c < 64; c++) {
            float xv = sX[c*65 + tt];
            const float* wr = sW + c*64 + eb;
            #pragma unroll
            for (int i = 0; i < 16; i++) acc[i] = fmaf(xv, wr[i], acc[i]);
        }
        float* outp = g_v + ((size_t)bh * Tt + tg) * DVv + half*64 + eb;
        #pragma unroll
        for (int i = 0; i < 16; i += 4)
            *(float4*)(outp + i) = make_float4(acc[i], acc[i+1], acc[i+2], acc[i+3]);
        __syncthreads();
    }
}

// ---------------- 6. recurrent scan ---------------------------------------
// S[c,v] <- a_t[c]*S[c,v] + kn_t[c]*v_t[v];  o_t[v] = sum_c q_t[c]*S[c,v]
// grid: 128 blocks = (b,h,vhalf); 256 threads: vi = tid>>2 (64 v-cols), cg = tid&3 (16 c each)
__global__ __launch_bounds__(256)
void scan_kernel()
{
    int blk   = blockIdx.x;
    int bh    = blk >> 1;
    int vhalf = blk & 1;
    int b = bh >> 3, h = bh & 7;
    int tid = threadIdx.x;
    int vi  = vhalf * 64 + (tid >> 2);
    int cg  = tid & 3;
    const float* qp = g_q + (size_t)bh * Tt * Cc;
    const float* vp = g_v + (size_t)bh * Tt * DVv + vi;
    const float* pp = g_proj + (size_t)b * Tt * NPROJ;
    float* op = g_o + (size_t)b * Tt * Dd + h * DVv + vi;

    __shared__ float sh[2][192];   // [ a(64) | kn(64) | q(64) ]
    float S[16];
    #pragma unroll
    for (int i = 0; i < 16; i++) S[i] = 0.f;

    // prologue: stage t=0
    if (tid < 64)       sh[0][tid] = pp[192 + h*64 + tid];
    else if (tid < 128) sh[0][tid] = pp[64 + (tid - 64)];
    else if (tid < 192) sh[0][tid] = qp[tid - 128];
    float vt = vp[0];
    __syncthreads();

    int buf = 0;
    for (int t = 0; t < Tt; t++) {
        float vt_next = 0.f;
        if (t + 1 < Tt) {   // prefetch t+1 into other buffer
            const float* prow = pp + (size_t)(t+1) * NPROJ;
            if (tid < 64)       sh[buf^1][tid] = prow[192 + h*64 + tid];
            else if (tid < 128) sh[buf^1][tid] = prow[64 + (tid - 64)];
            else if (tid < 192) sh[buf^1][tid] = qp[(size_t)(t+1)*Cc + (tid - 128)];
            vt_next = vp[(size_t)(t+1) * DVv];
        }
        const float* base = sh[buf];
        float acc = 0.f;
        #pragma unroll
        for (int j = 0; j < 4; j++) {
            float4 a4 = *(const float4*)(base +       cg*16 + 4*j);
            float4 k4 = *(const float4*)(base +  64 + cg*16 + 4*j);
            float4 q4 = *(const float4*)(base + 128 + cg*16 + 4*j);
            S[4*j+0] = fmaf(a4.x, S[4*j+0], k4.x*vt); acc = fmaf(q4.x, S[4*j+0], acc);
            S[4*j+1] = fmaf(a4.y, S[4*j+1], k4.y*vt); acc = fmaf(q4.y, S[4*j+1], acc);
            S[4*j+2] = fmaf(a4.z, S[4*j+2], k4.z*vt); acc = fmaf(q4.z, S[4*j+2], acc);
            S[4*j+3] = fmaf(a4.w, S[4*j+3], k4.w*vt); acc = fmaf(q4.w, S[4*j+3], acc);
        }
        acc += __shfl_xor_sync(0xffffffffu, acc, 1);
        acc += __shfl_xor_sync(0xffffffffu, acc, 2);
        if (cg == 0) op[(size_t)t * Dd] = acc;
        vt = vt_next;
        __syncthreads();
        buf ^= 1;
    }
}

// ---------------- launch ---------------------------------------------------
extern "C" void kernel_launch(void* const* d_in, const int* in_sizes, int n_in,
                              void* d_out, int out_size)
{
    const float* x     = (const float*)d_in[0];
    const float* Wq    = (const float*)d_in[1];
    const float* Wk    = (const float*)d_in[2];
    const float* Wv    = (const float*)d_in[3];
    const float* Qc    = (const float*)d_in[4];
    const float* Vc    = (const float*)d_in[5];
    const float* Wa_w  = (const float*)d_in[6];
    const float* Wa_b  = (const float*)d_in[7];
    const float* Wo    = (const float*)d_in[8];
    const float* gamma = (const float*)d_in[9];
    const float* beta  = (const float*)d_in[10];
    float* out = (float*)d_out;

    float *xn, *wall, *proj, *o;
    cudaGetSymbolAddress((void**)&xn,   g_xn);
    cudaGetSymbolAddress((void**)&wall, g_wall);
    cudaGetSymbolAddress((void**)&proj, g_proj);
    cudaGetSymbolAddress((void**)&o,    g_o);

    // 1. layernorm
    ln_kernel<<<Mm, 256>>>(x, gamma, beta);
    // 2. concat projection weights
    build_wall<<<(NPROJ*Dd)/256, 256>>>(Wq, Wk, Wv, Wa_w);
    // 3. fused projection GEMM: proj = xn @ wall^T   (16384 x 704, K=1024)
    sgemm_nt<<<dim3((NPROJ+127)/128, Mm/128), 256>>>(Mm, NPROJ, Dd, xn, wall, proj, nullptr);
    // 4. normalize k, sigmoid alpha
    epi_kernel<<<Mm, 128>>>(Wa_b);
    // 5. per-head q rotation + v up-projection
    head_kernel<<<dim3(Mm/64, Hh), 256>>>(Qc, Vc);
    // 6. recurrent scan
    scan_kernel<<<128, 256>>>();
    // 7. output GEMM + residual: out = o @ Wo^T + x   (16384 x 1024, K=1024)
    sgemm_nt<<<dim3(Dd/128, Mm/128), 256>>>(Mm, Dd, Dd, o, Wo, out, x);
}

// round 3
// speedup vs baseline: 1.3001x; 1.3001x over previous
#include <cuda_runtime.h>
#include <cstdint>
#include <math.h>

// Problem constants
#define Bb   8
#define Tt   2048
#define Dd   1024
#define Hh   8
#define Cc   64
#define DVv  128
#define Mm   (Bb*Tt)        // 16384 token rows
#define NPROJ 704           // q(64) | k(64) | v(64) | alpha(512)
#define PSTR  768           // padded projection stride (multiple of 128)

// ---------------- scratch (device globals; no allocation allowed) ----------
__device__ float g_xn  [(size_t)Mm*Dd];       // layernormed x
__device__ float g_wall[(size_t)PSTR*Dd];     // concat(Wq,Wk,Wv,Wa) padded to 768 rows
__device__ float g_proj[(size_t)Mm*PSTR];     // q_lat|kn|v_lat|alpha (stride 768)
__device__ float g_q   [(size_t)Bb*Hh*Tt*Cc];
__device__ float g_v   [(size_t)Bb*Hh*Tt*DVv];
__device__ float g_o   [(size_t)Mm*Dd];

// ---------------- 1. LayerNorm -------------------------------------------
__global__ __launch_bounds__(256)
void ln_kernel(const float* __restrict__ x, const float* __restrict__ gamma,
               const float* __restrict__ beta)
{
    int row = blockIdx.x;
    int tid = threadIdx.x;
    const float4* xr = (const float4*)(x + (size_t)row*Dd);
    float4 v = xr[tid];
    float s  = v.x + v.y + v.z + v.w;
    float s2 = v.x*v.x + v.y*v.y + v.z*v.z + v.w*v.w;
    #pragma unroll
    for (int o = 16; o > 0; o >>= 1) {
        s  += __shfl_xor_sync(0xffffffffu, s,  o);
        s2 += __shfl_xor_sync(0xffffffffu, s2, o);
    }
    __shared__ float r1[8], r2[8];
    int w = tid >> 5, l = tid & 31;
    if (l == 0) { r1[w] = s; r2[w] = s2; }
    __syncthreads();
    s = 0.f; s2 = 0.f;
    #pragma unroll
    for (int i = 0; i < 8; i++) { s += r1[i]; s2 += r2[i]; }
    float mu  = s * (1.f/Dd);
    float var = s2 * (1.f/Dd) - mu*mu;
    float inv = rsqrtf(var + 1e-5f);
    float4 g  = ((const float4*)gamma)[tid];
    float4 be = ((const float4*)beta)[tid];
    float4 o;
    o.x = (v.x - mu)*inv*g.x + be.x;
    o.y = (v.y - mu)*inv*g.y + be.y;
    o.z = (v.z - mu)*inv*g.z + be.z;
    o.w = (v.w - mu)*inv*g.w + be.w;
    ((float4*)(g_xn + (size_t)row*Dd))[tid] = o;
}

// ---------------- 2. concat weights (Wq|Wk|Wv|Wa), zero-pad to 768 --------
__global__ void build_wall(const float* __restrict__ Wq, const float* __restrict__ Wk,
                           const float* __restrict__ Wv, const float* __restrict__ Wa)
{
    int i = blockIdx.x * blockDim.x + threadIdx.x;   // 0 .. 768*1024-1
    int row = i >> 10, col = i & 1023;
    float val;
    if      (row <  64) val = Wq[(size_t)row       *1024 + col];
    else if (row < 128) val = Wk[(size_t)(row- 64) *1024 + col];
    else if (row < 192) val = Wv[(size_t)(row-128) *1024 + col];
    else if (row < 704) val = Wa[(size_t)(row-192) *1024 + col];
    else                val = 0.f;
    g_wall[i] = val;
}

// ---------------- 3. TF32 tensor-core GEMM  Y[M,N] = A[M,K] @ W[N,K]^T ----
// BM=BN=128, BK=16, 256 threads, warp grid 2x4 (64x32 per warp), double-buffered.
// Smem layout [row][k] with pad to 20 -> conflict-free fragment loads.
__device__ __forceinline__ uint32_t f2tf32(float f) {
    uint32_t u;
    asm volatile("cvt.rna.tf32.f32 %0, %1;" : "=r"(u) : "f"(f));
    return u;
}
__device__ __forceinline__ void mma_tf32(float c[4], const uint32_t a[4], const uint32_t b[2]) {
    asm volatile(
        "mma.sync.aligned.m16n8k8.row.col.f32.tf32.tf32.f32 "
        "{%0,%1,%2,%3}, {%4,%5,%6,%7}, {%8,%9}, {%0,%1,%2,%3};\n"
        : "+f"(c[0]), "+f"(c[1]), "+f"(c[2]), "+f"(c[3])
        : "r"(a[0]), "r"(a[1]), "r"(a[2]), "r"(a[3]), "r"(b[0]), "r"(b[1]));
}

__global__ __launch_bounds__(256, 2)
void gemm_tf32(int Ns, int K,
               const float* __restrict__ A,
               const float* __restrict__ W,
               float* __restrict__ Y,
               const float* __restrict__ resid)
{
    __shared__ uint32_t As[2][128*20];
    __shared__ uint32_t Bs[2][128*20];

    int tid  = threadIdx.x;
    int lane = tid & 31, warp = tid >> 5;
    int wm = warp & 1, wn = warp >> 1;        // 2 x 4 warp grid
    int g  = lane >> 2, tig = lane & 3;
    int row0 = blockIdx.y * 128;
    int col0 = blockIdx.x * 128;

    // loader mapping: 512 float4 per tile, 2 per thread
    int lrow = tid >> 2;            // 0..63 (and +64)
    int kc   = (tid & 3) * 4;
    const float* Ap = A + (size_t)(row0 + lrow) * K + kc;
    const float* Bp = W + (size_t)(col0 + lrow) * K + kc;

    float acc[4][4][4];
    #pragma unroll
    for (int i = 0; i < 4; i++)
        #pragma unroll
        for (int j = 0; j < 4; j++)
            #pragma unroll
            for (int e = 0; e < 4; e++) acc[i][j][e] = 0.f;

    // preload k0 = 0
    {
        float4 a0 = *(const float4*)(Ap);
        float4 a1 = *(const float4*)(Ap + (size_t)64*K);
        float4 b0 = *(const float4*)(Bp);
        float4 b1 = *(const float4*)(Bp + (size_t)64*K);
        *(uint4*)&As[0][lrow*20 + kc]      = make_uint4(f2tf32(a0.x), f2tf32(a0.y), f2tf32(a0.z), f2tf32(a0.w));
        *(uint4*)&As[0][(lrow+64)*20 + kc] = make_uint4(f2tf32(a1.x), f2tf32(a1.y), f2tf32(a1.z), f2tf32(a1.w));
        *(uint4*)&Bs[0][lrow*20 + kc]      = make_uint4(f2tf32(b0.x), f2tf32(b0.y), f2tf32(b0.z), f2tf32(b0.w));
        *(uint4*)&Bs[0][(lrow+64)*20 + kc] = make_uint4(f2tf32(b1.x), f2tf32(b1.y), f2tf32(b1.z), f2tf32(b1.w));
    }
    __syncthreads();

    int buf = 0;
    for (int k0 = 0; k0 < K; k0 += 16) {
        float4 pa0, pa1, pb0, pb1;
        bool more = (k0 + 16) < K;
        if (more) {
            pa0 = *(const float4*)(Ap + k0 + 16);
            pa1 = *(const float4*)(Ap + (size_t)64*K + k0 + 16);
            pb0 = *(const float4*)(Bp + k0 + 16);
            pb1 = *(const float4*)(Bp + (size_t)64*K + k0 + 16);
        }

        const uint32_t* Ab  = As[buf];
        const uint32_t* Bb_ = Bs[buf];
        #pragma unroll
        for (int ks = 0; ks < 16; ks += 8) {
            uint32_t af[4][4], bf[4][2];
            #pragma unroll
            for (int i = 0; i < 4; i++) {
                int base = (wm*64 + i*16 + g)*20 + ks + tig;
                af[i][0] = Ab[base];
                af[i][1] = Ab[base + 8*20];
                af[i][2] = Ab[base + 4];
                af[i][3] = Ab[base + 8*20 + 4];
            }
            #pragma unroll
            for (int j = 0; j < 4; j++) {
                int base = (wn*32 + j*8 + g)*20 + ks + tig;
                bf[j][0] = Bb_[base];
                bf[j][1] = Bb_[base + 4];
            }
            #pragma unroll
            for (int i = 0; i < 4; i++)
                #pragma unroll
                for (int j = 0; j < 4; j++)
                    mma_tf32(acc[i][j], af[i], bf[j]);
        }

        if (more) {
            int nb = buf ^ 1;
            *(uint4*)&As[nb][lrow*20 + kc]      = make_uint4(f2tf32(pa0.x), f2tf32(pa0.y), f2tf32(pa0.z), f2tf32(pa0.w));
            *(uint4*)&As[nb][(lrow+64)*20 + kc] = make_uint4(f2tf32(pa1.x), f2tf32(pa1.y), f2tf32(pa1.z), f2tf32(pa1.w));
            *(uint4*)&Bs[nb][lrow*20 + kc]      = make_uint4(f2tf32(pb0.x), f2tf32(pb0.y), f2tf32(pb0.z), f2tf32(pb0.w));
            *(uint4*)&Bs[nb][(lrow+64)*20 + kc] = make_uint4(f2tf32(pb1.x), f2tf32(pb1.y), f2tf32(pb1.z), f2tf32(pb1.w));
            __syncthreads();
            buf = nb;
        }
    }

    // epilogue: c fragment (m = g + {0,8}, n = tig*2 + {0,1})
    #pragma unroll
    for (int i = 0; i < 4; i++) {
        #pragma unroll
        for (int j = 0; j < 4; j++) {
            int m0 = row0 + wm*64 + i*16 + g;
            int n0 = col0 + wn*32 + j*8 + tig*2;
            #pragma unroll
            for (int half = 0; half < 2; half++) {
                int m = m0 + half*8;
                float2 val = make_float2(acc[i][j][half*2], acc[i][j][half*2+1]);
                if (resid) {
                    const float2 r = *(const float2*)(resid + (size_t)m*Ns + n0);
                    val.x += r.x; val.y += r.y;
                }
                *(float2*)(Y + (size_t)m*Ns + n0) = val;
            }
        }
    }
}

// ---------------- 4. epilogue: normalize k, sigmoid(alpha + bias) ---------
__global__ __launch_bounds__(128)
void epi_kernel(const float* __restrict__ Wa_b)
{
    int row = blockIdx.x;
    float* p = g_proj + (size_t)row * PSTR;
    int tid = threadIdx.x;
    float kv = 0.f, sq = 0.f;
    if (tid < 64) { kv = p[64 + tid]; sq = kv * kv; }
    #pragma unroll
    for (int o = 16; o > 0; o >>= 1) sq += __shfl_xor_sync(0xffffffffu, sq, o);
    __shared__ float part[2];
    if ((tid & 31) == 0 && tid < 64) part[tid >> 5] = sq;
    __syncthreads();
    float inv = 1.f / fmaxf(sqrtf(part[0] + part[1]), 1e-12f);
    if (tid < 64) p[64 + tid] = kv * inv;
    #pragma unroll
    for (int r = 0; r < 4; r++) {
        int j = tid + r * 128;
        float a = p[192 + j] + Wa_b[j];
        p[192 + j] = 1.f / (1.f + expf(-a));
    }
}

// ---------------- 5. per-head transforms: q = qlat@Qc[h], v = vlat@Vc[h] --
__global__ __launch_bounds__(256)
void head_kernel(const float* __restrict__ Qc, const float* __restrict__ Vc)
{
    __shared__ float sX[Cc * 65];   // [c][t], padded
    __shared__ float sW[Cc * 64];   // [c][e]
    int h    = blockIdx.y;
    int row0 = blockIdx.x * 64;
    int tid  = threadIdx.x;
    int bh   = (row0 >> 11) * Hh + h;
    int tt   = tid >> 2;
    int eb   = (tid & 3) * 16;
    int tg   = (row0 + tt) & (Tt - 1);

    // --- Q phase ---
    #pragma unroll
    for (int it = 0; it < 4; it++) {
        int i = tid + it * 256;
        int t = i >> 4, c4 = (i & 15) * 4;
        float4 xv = *(const float4*)(g_proj + (size_t)(row0 + t) * PSTR + c4);
        sX[(c4+0)*65 + t] = xv.x; sX[(c4+1)*65 + t] = xv.y;
        sX[(c4+2)*65 + t] = xv.z; sX[(c4+3)*65 + t] = xv.w;
    }
    {
        const float4* src = (const float4*)(Qc + (size_t)h * Cc * Cc);
        float4* dst = (float4*)sW;
        #pragma unroll
        for (int it = 0; it < 4; it++) dst[tid + it*256] = src[tid + it*256];
    }
    __syncthreads();
    {
        float acc[16];
        #pragma unroll
        for (int i = 0; i < 16; i++) acc[i] = 0.f;
        #pragma unroll
        for (int c = 0; c < 64; c++) {
            float xv = sX[c*65 + tt];
            const float* wr = sW + c*64 + eb;
            #pragma unroll
            for (int i = 0; i < 16; i++) acc[i] = fmaf(xv, wr[i], acc[i]);
        }
        float* outp = g_q + ((size_t)bh * Tt + tg) * Cc + eb;
        #pragma unroll
        for (int i = 0; i < 16; i += 4)
            *(float4*)(outp + i) = make_float4(acc[i], acc[i+1], acc[i+2], acc[i+3]);
    }
    __syncthreads();

    // --- V phase ---
    #pragma unroll
    for (int it = 0; it < 4; it++) {
        int i = tid + it * 256;
        int t = i >> 4, c4 = (i & 15) * 4;
        float4 xv = *(const float4*)(g_proj + (size_t)(row0 + t) * PSTR + 128 + c4);
        sX[(c4+0)*65 + t] = xv.x; sX[(c4+1)*65 + t] = xv.y;
        sX[(c4+2)*65 + t] = xv.z; sX[(c4+3)*65 + t] = xv.w;
    }
    for (int half = 0; half < 2; half++) {
        #pragma unroll
        for (int it = 0; it < 4; it++) {
            int i = tid + it * 256;
            int c = i >> 4, e4 = (i & 15) * 4;
            float4 wv = *(const float4*)(Vc + (size_t)h*Cc*DVv + (size_t)c*DVv + half*64 + e4);
            *(float4*)(sW + c*64 + e4) = wv;
        }
        __syncthreads();
        float acc[16];
        #pragma unroll
        for (int i = 0; i < 16; i++) acc[i] = 0.f;
        #pragma unroll
        for (int c = 0; c < 64; c++) {
            float xv = sX[c*65 + tt];
            const float* wr = sW + c*64 + eb;
            #pragma unroll
            for (int i = 0; i < 16; i++) acc[i] = fmaf(xv, wr[i], acc[i]);
        }
        float* outp = g_v + ((size_t)bh * Tt + tg) * DVv + half*64 + eb;
        #pragma unroll
        for (int i = 0; i < 16; i += 4)
            *(float4*)(outp + i) = make_float4(acc[i], acc[i+1], acc[i+2], acc[i+3]);
        __syncthreads();
    }
}

// ---------------- 6. recurrent scan ---------------------------------------
__global__ __launch_bounds__(256)
void scan_kernel()
{
    int blk   = blockIdx.x;
    int bh    = blk >> 1;
    int vhalf = blk & 1;
    int b = bh >> 3, h = bh & 7;
    int tid = threadIdx.x;
    int vi  = vhalf * 64 + (tid >> 2);
    int cg  = tid & 3;
    const float* qp = g_q + (size_t)bh * Tt * Cc;
    const float* vp = g_v + (size_t)bh * Tt * DVv + vi;
    const float* pp = g_proj + (size_t)b * Tt * PSTR;
    float* op = g_o + (size_t)b * Tt * Dd + h * DVv + vi;

    __shared__ float sh[2][192];   // [ a(64) | kn(64) | q(64) ]
    float S[16];
    #pragma unroll
    for (int i = 0; i < 16; i++) S[i] = 0.f;

    if (tid < 64)       sh[0][tid] = pp[192 + h*64 + tid];
    else if (tid < 128) sh[0][tid] = pp[64 + (tid - 64)];
    else if (tid < 192) sh[0][tid] = qp[tid - 128];
    float vt = vp[0];
    __syncthreads();

    int buf = 0;
    for (int t = 0; t < Tt; t++) {
        float vt_next = 0.f;
        if (t + 1 < Tt) {
            const float* prow = pp + (size_t)(t+1) * PSTR;
            if (tid < 64)       sh[buf^1][tid] = prow[192 + h*64 + tid];
            else if (tid < 128) sh[buf^1][tid] = prow[64 + (tid - 64)];
            else if (tid < 192) sh[buf^1][tid] = qp[(size_t)(t+1)*Cc + (tid - 128)];
            vt_next = vp[(size_t)(t+1) * DVv];
        }
        const float* base = sh[buf];
        float acc = 0.f;
        #pragma unroll
        for (int j = 0; j < 4; j++) {
            float4 a4 = *(const float4*)(base +       cg*16 + 4*j);
            float4 k4 = *(const float4*)(base +  64 + cg*16 + 4*j);
            float4 q4 = *(const float4*)(base + 128 + cg*16 + 4*j);
            S[4*j+0] = fmaf(a4.x, S[4*j+0], k4.x*vt); acc = fmaf(q4.x, S[4*j+0], acc);
            S[4*j+1] = fmaf(a4.y, S[4*j+1], k4.y*vt); acc = fmaf(q4.y, S[4*j+1], acc);
            S[4*j+2] = fmaf(a4.z, S[4*j+2], k4.z*vt); acc = fmaf(q4.z, S[4*j+2], acc);
            S[4*j+3] = fmaf(a4.w, S[4*j+3], k4.w*vt); acc = fmaf(q4.w, S[4*j+3], acc);
        }
        acc += __shfl_xor_sync(0xffffffffu, acc, 1);
        acc += __shfl_xor_sync(0xffffffffu, acc, 2);
        if (cg == 0) op[(size_t)t * Dd] = acc;
        vt = vt_next;
        __syncthreads();
        buf ^= 1;
    }
}

// ---------------- launch ---------------------------------------------------
extern "C" void kernel_launch(void* const* d_in, const int* in_sizes, int n_in,
                              void* d_out, int out_size)
{
    const float* x     = (const float*)d_in[0];
    const float* Wq    = (const float*)d_in[1];
    const float* Wk    = (const float*)d_in[2];
    const float* Wv    = (const float*)d_in[3];
    const float* Qc    = (const float*)d_in[4];
    const float* Vc    = (const float*)d_in[5];
    const float* Wa_w  = (const float*)d_in[6];
    const float* Wa_b  = (const float*)d_in[7];
    const float* Wo    = (const float*)d_in[8];
    const float* gamma = (const float*)d_in[9];
    const float* beta  = (const float*)d_in[10];
    float* out = (float*)d_out;

    float *xn, *wall, *proj, *o;
    cudaGetSymbolAddress((void**)&xn,   g_xn);
    cudaGetSymbolAddress((void**)&wall, g_wall);
    cudaGetSymbolAddress((void**)&proj, g_proj);
    cudaGetSymbolAddress((void**)&o,    g_o);

    // 1. layernorm
    ln_kernel<<<Mm, 256>>>(x, gamma, beta);
    // 2. concat projection weights (padded to 768 rows)
    build_wall<<<(PSTR*Dd)/256, 256>>>(Wq, Wk, Wv, Wa_w);
    // 3. fused projection GEMM: proj[16384,768] = xn @ wall^T (K=1024), tensor cores
    gemm_tf32<<<dim3(PSTR/128, Mm/128), 256>>>(PSTR, Dd, xn, wall, proj, nullptr);
    // 4. normalize k, sigmoid alpha
    epi_kernel<<<Mm, 128>>>(Wa_b);
    // 5. per-head q rotation + v up-projection
    head_kernel<<<dim3(Mm/64, Hh), 256>>>(Qc, Vc);
    // 6. recurrent scan
    scan_kernel<<<128, 256>>>();
    // 7. output GEMM + residual: out = o @ Wo^T + x (16384x1024, K=1024), tensor cores
    gemm_tf32<<<dim3(Dd/128, Mm/128), 256>>>(Dd, Dd, o, Wo, out, x);
}

// round 5
// speedup vs baseline: 2.2891x; 1.7607x over previous
#include <cuda_runtime.h>
#include <cstdint>
#include <math.h>

// Problem constants
#define Bb   8
#define Tt   2048
#define Dd   1024
#define Hh   8
#define Cc   64
#define DVv  128
#define Mm   (Bb*Tt)        // 16384 token rows
#define NPROJ 704           // q(64) | k(64) | v(64) | alpha(512)
#define PSTR  768           // padded projection stride (multiple of 128)
#define CH   16             // scan chunk (timesteps staged per smem buffer)

// ---------------- scratch (device globals; no allocation allowed) ----------
__device__ float g_xn  [(size_t)Mm*Dd];
__device__ float g_wall[(size_t)PSTR*Dd];
__device__ float g_proj[(size_t)Mm*PSTR];
__device__ float g_q   [(size_t)Bb*Hh*Tt*Cc];
__device__ float g_v   [(size_t)Bb*Hh*Tt*DVv];
__device__ float g_o   [(size_t)Mm*Dd];

// ---------------- 1. LayerNorm -------------------------------------------
__global__ __launch_bounds__(256)
void ln_kernel(const float* __restrict__ x, const float* __restrict__ gamma,
               const float* __restrict__ beta)
{
    int row = blockIdx.x;
    int tid = threadIdx.x;
    const float4* xr = (const float4*)(x + (size_t)row*Dd);
    float4 v = xr[tid];
    float s  = v.x + v.y + v.z + v.w;
    float s2 = v.x*v.x + v.y*v.y + v.z*v.z + v.w*v.w;
    #pragma unroll
    for (int o = 16; o > 0; o >>= 1) {
        s  += __shfl_xor_sync(0xffffffffu, s,  o);
        s2 += __shfl_xor_sync(0xffffffffu, s2, o);
    }
    __shared__ float r1[8], r2[8];
    int w = tid >> 5, l = tid & 31;
    if (l == 0) { r1[w] = s; r2[w] = s2; }
    __syncthreads();
    s = 0.f; s2 = 0.f;
    #pragma unroll
    for (int i = 0; i < 8; i++) { s += r1[i]; s2 += r2[i]; }
    float mu  = s * (1.f/Dd);
    float var = s2 * (1.f/Dd) - mu*mu;
    float inv = rsqrtf(var + 1e-5f);
    float4 g  = ((const float4*)gamma)[tid];
    float4 be = ((const float4*)beta)[tid];
    float4 o;
    o.x = (v.x - mu)*inv*g.x + be.x;
    o.y = (v.y - mu)*inv*g.y + be.y;
    o.z = (v.z - mu)*inv*g.z + be.z;
    o.w = (v.w - mu)*inv*g.w + be.w;
    ((float4*)(g_xn + (size_t)row*Dd))[tid] = o;
}

// ---------------- 2. concat weights (Wq|Wk|Wv|Wa), zero-pad to 768 --------
__global__ void build_wall(const float* __restrict__ Wq, const float* __restrict__ Wk,
                           const float* __restrict__ Wv, const float* __restrict__ Wa)
{
    int i = blockIdx.x * blockDim.x + threadIdx.x;
    int row = i >> 10, col = i & 1023;
    float val;
    if      (row <  64) val = Wq[(size_t)row       *1024 + col];
    else if (row < 128) val = Wk[(size_t)(row- 64) *1024 + col];
    else if (row < 192) val = Wv[(size_t)(row-128) *1024 + col];
    else if (row < 704) val = Wa[(size_t)(row-192) *1024 + col];
    else                val = 0.f;
    g_wall[i] = val;
}

// ---------------- 3. TF32 tensor-core GEMM  Y[M,N] = A[M,K] @ W[N,K]^T ----
__device__ __forceinline__ uint32_t f2tf32(float f) {
    uint32_t u;
    asm volatile("cvt.rna.tf32.f32 %0, %1;" : "=r"(u) : "f"(f));
    return u;
}
__device__ __forceinline__ void mma_tf32(float c[4], const uint32_t a[4], const uint32_t b[2]) {
    asm volatile(
        "mma.sync.aligned.m16n8k8.row.col.f32.tf32.tf32.f32 "
        "{%0,%1,%2,%3}, {%4,%5,%6,%7}, {%8,%9}, {%0,%1,%2,%3};\n"
        : "+f"(c[0]), "+f"(c[1]), "+f"(c[2]), "+f"(c[3])
        : "r"(a[0]), "r"(a[1]), "r"(a[2]), "r"(a[3]), "r"(b[0]), "r"(b[1]));
}

__global__ __launch_bounds__(256, 2)
void gemm_tf32(int Ns, int K,
               const float* __restrict__ A,
               const float* __restrict__ W,
               float* __restrict__ Y,
               const float* __restrict__ resid)
{
    __shared__ uint32_t As[2][128*20];
    __shared__ uint32_t Bs[2][128*20];

    int tid  = threadIdx.x;
    int lane = tid & 31, warp = tid >> 5;
    int wm = warp & 1, wn = warp >> 1;
    int g  = lane >> 2, tig = lane & 3;
    int row0 = blockIdx.y * 128;
    int col0 = blockIdx.x * 128;

    int lrow = tid >> 2;
    int kc   = (tid & 3) * 4;
    const float* Ap = A + (size_t)(row0 + lrow) * K + kc;
    const float* Bp = W + (size_t)(col0 + lrow) * K + kc;

    float acc[4][4][4];
    #pragma unroll
    for (int i = 0; i < 4; i++)
        #pragma unroll
        for (int j = 0; j < 4; j++)
            #pragma unroll
            for (int e = 0; e < 4; e++) acc[i][j][e] = 0.f;

    {
        float4 a0 = *(const float4*)(Ap);
        float4 a1 = *(const float4*)(Ap + (size_t)64*K);
        float4 b0 = *(const float4*)(Bp);
        float4 b1 = *(const float4*)(Bp + (size_t)64*K);
        *(uint4*)&As[0][lrow*20 + kc]      = make_uint4(f2tf32(a0.x), f2tf32(a0.y), f2tf32(a0.z), f2tf32(a0.w));
        *(uint4*)&As[0][(lrow+64)*20 + kc] = make_uint4(f2tf32(a1.x), f2tf32(a1.y), f2tf32(a1.z), f2tf32(a1.w));
        *(uint4*)&Bs[0][lrow*20 + kc]      = make_uint4(f2tf32(b0.x), f2tf32(b0.y), f2tf32(b0.z), f2tf32(b0.w));
        *(uint4*)&Bs[0][(lrow+64)*20 + kc] = make_uint4(f2tf32(b1.x), f2tf32(b1.y), f2tf32(b1.z), f2tf32(b1.w));
    }
    __syncthreads();

    int buf = 0;
    for (int k0 = 0; k0 < K; k0 += 16) {
        float4 pa0, pa1, pb0, pb1;
        bool more = (k0 + 16) < K;
        if (more) {
            pa0 = *(const float4*)(Ap + k0 + 16);
            pa1 = *(const float4*)(Ap + (size_t)64*K + k0 + 16);
            pb0 = *(const float4*)(Bp + k0 + 16);
            pb1 = *(const float4*)(Bp + (size_t)64*K + k0 + 16);
        }

        const uint32_t* Ab  = As[buf];
        const uint32_t* Bb_ = Bs[buf];
        #pragma unroll
        for (int ks = 0; ks < 16; ks += 8) {
            uint32_t af[4][4], bf[4][2];
            #pragma unroll
            for (int i = 0; i < 4; i++) {
                int base = (wm*64 + i*16 + g)*20 + ks + tig;
                af[i][0] = Ab[base];
                af[i][1] = Ab[base + 8*20];
                af[i][2] = Ab[base + 4];
                af[i][3] = Ab[base + 8*20 + 4];
            }
            #pragma unroll
            for (int j = 0; j < 4; j++) {
                int base = (wn*32 + j*8 + g)*20 + ks + tig;
                bf[j][0] = Bb_[base];
                bf[j][1] = Bb_[base + 4];
            }
            #pragma unroll
            for (int i = 0; i < 4; i++)
                #pragma unroll
                for (int j = 0; j < 4; j++)
                    mma_tf32(acc[i][j], af[i], bf[j]);
        }

        if (more) {
            int nb = buf ^ 1;
            *(uint4*)&As[nb][lrow*20 + kc]      = make_uint4(f2tf32(pa0.x), f2tf32(pa0.y), f2tf32(pa0.z), f2tf32(pa0.w));
            *(uint4*)&As[nb][(lrow+64)*20 + kc] = make_uint4(f2tf32(pa1.x), f2tf32(pa1.y), f2tf32(pa1.z), f2tf32(pa1.w));
            *(uint4*)&Bs[nb][lrow*20 + kc]      = make_uint4(f2tf32(pb0.x), f2tf32(pb0.y), f2tf32(pb0.z), f2tf32(pb0.w));
            *(uint4*)&Bs[nb][(lrow+64)*20 + kc] = make_uint4(f2tf32(pb1.x), f2tf32(pb1.y), f2tf32(pb1.z), f2tf32(pb1.w));
            __syncthreads();
            buf = nb;
        }
    }

    #pragma unroll
    for (int i = 0; i < 4; i++) {
        #pragma unroll
        for (int j = 0; j < 4; j++) {
            int m0 = row0 + wm*64 + i*16 + g;
            int n0 = col0 + wn*32 + j*8 + tig*2;
            #pragma unroll
            for (int half = 0; half < 2; half++) {
                int m = m0 + half*8;
                float2 val = make_float2(acc[i][j][half*2], acc[i][j][half*2+1]);
                if (resid) {
                    const float2 r = *(const float2*)(resid + (size_t)m*Ns + n0);
                    val.x += r.x; val.y += r.y;
                }
                *(float2*)(Y + (size_t)m*Ns + n0) = val;
            }
        }
    }
}

// ---------------- 4. epilogue: normalize k, sigmoid(alpha + bias) ---------
__global__ __launch_bounds__(128)
void epi_kernel(const float* __restrict__ Wa_b)
{
    int row = blockIdx.x;
    float* p = g_proj + (size_t)row * PSTR;
    int tid = threadIdx.x;
    float kv = 0.f, sq = 0.f;
    if (tid < 64) { kv = p[64 + tid]; sq = kv * kv; }
    #pragma unroll
    for (int o = 16; o > 0; o >>= 1) sq += __shfl_xor_sync(0xffffffffu, sq, o);
    __shared__ float part[2];
    if ((tid & 31) == 0 && tid < 64) part[tid >> 5] = sq;
    __syncthreads();
    float inv = 1.f / fmaxf(sqrtf(part[0] + part[1]), 1e-12f);
    if (tid < 64) p[64 + tid] = kv * inv;
    #pragma unroll
    for (int r = 0; r < 4; r++) {
        int j = tid + r * 128;
        float a = p[192 + j] + Wa_b[j];
        p[192 + j] = 1.f / (1.f + expf(-a));
    }
}

// ---------------- 5. per-head transforms ----------------------------------
__global__ __launch_bounds__(256)
void head_kernel(const float* __restrict__ Qc, const float* __restrict__ Vc)
{
    __shared__ float sX[Cc * 65];
    __shared__ float sW[Cc * 64];
    int h    = blockIdx.y;
    int row0 = blockIdx.x * 64;
    int tid  = threadIdx.x;
    int bh   = (row0 >> 11) * Hh + h;
    int tt   = tid >> 2;
    int eb   = (tid & 3) * 16;
    int tg   = (row0 + tt) & (Tt - 1);

    #pragma unroll
    for (int it = 0; it < 4; it++) {
        int i = tid + it * 256;
        int t = i >> 4, c4 = (i & 15) * 4;
        float4 xv = *(const float4*)(g_proj + (size_t)(row0 + t) * PSTR + c4);
        sX[(c4+0)*65 + t] = xv.x; sX[(c4+1)*65 + t] = xv.y;
        sX[(c4+2)*65 + t] = xv.z; sX[(c4+3)*65 + t] = xv.w;
    }
    {
        const float4* src = (const float4*)(Qc + (size_t)h * Cc * Cc);
        float4* dst = (float4*)sW;
        #pragma unroll
        for (int it = 0; it < 4; it++) dst[tid + it*256] = src[tid + it*256];
    }
    __syncthreads();
    {
        float acc[16];
        #pragma unroll
        for (int i = 0; i < 16; i++) acc[i] = 0.f;
        #pragma unroll
        for (int c = 0; c < 64; c++) {
            float xv = sX[c*65 + tt];
            const float* wr = sW + c*64 + eb;
            #pragma unroll
            for (int i = 0; i < 16; i++) acc[i] = fmaf(xv, wr[i], acc[i]);
        }
        float* outp = g_q + ((size_t)bh * Tt + tg) * Cc + eb;
        #pragma unroll
        for (int i = 0; i < 16; i += 4)
            *(float4*)(outp + i) = make_float4(acc[i], acc[i+1], acc[i+2], acc[i+3]);
    }
    __syncthreads();

    #pragma unroll
    for (int it = 0; it < 4; it++) {
        int i = tid + it * 256;
        int t = i >> 4, c4 = (i & 15) * 4;
        float4 xv = *(const float4*)(g_proj + (size_t)(row0 + t) * PSTR + 128 + c4);
        sX[(c4+0)*65 + t] = xv.x; sX[(c4+1)*65 + t] = xv.y;
        sX[(c4+2)*65 + t] = xv.z; sX[(c4+3)*65 + t] = xv.w;
    }
    for (int half = 0; half < 2; half++) {
        #pragma unroll
        for (int it = 0; it < 4; it++) {
            int i = tid + it * 256;
            int c = i >> 4, e4 = (i & 15) * 4;
            float4 wv = *(const float4*)(Vc + (size_t)h*Cc*DVv + (size_t)c*DVv + half*64 + e4);
            *(float4*)(sW + c*64 + e4) = wv;
        }
        __syncthreads();
        float acc[16];
        #pragma unroll
        for (int i = 0; i < 16; i++) acc[i] = 0.f;
        #pragma unroll
        for (int c = 0; c < 64; c++) {
            float xv = sX[c*65 + tt];
            const float* wr = sW + c*64 + eb;
            #pragma unroll
            for (int i = 0; i < 16; i++) acc[i] = fmaf(xv, wr[i], acc[i]);
        }
        float* outp = g_v + ((size_t)bh * Tt + tg) * DVv + half*64 + eb;
        #pragma unroll
        for (int i = 0; i < 16; i += 4)
            *(float4*)(outp + i) = make_float4(acc[i], acc[i+1], acc[i+2], acc[i+3]);
        __syncthreads();
    }
}

// ---------------- 6. recurrent scan (chunked, latency-hidden) --------------
// Per block: (b,h,vhalf). Stage CH=16 steps of [a|k|q|v] rows (256 floats each)
// into double-buffered smem; prefetch next chunk into regs during compute.
// Thread layout: vi = tid>>2 (64 v-cols), cg = tid&3 (16 c's each).
__global__ __launch_bounds__(256)
void scan_kernel()
{
    int blk   = blockIdx.x;
    int bh    = blk >> 1;
    int vhalf = blk & 1;
    int b = bh >> 3, h = bh & 7;
    int tid = threadIdx.x;
    int vi  = tid >> 2;
    int cg  = tid & 3;
    const float* qp = g_q + (size_t)bh * Tt * Cc;
    const float* vp = g_v + (size_t)bh * Tt * DVv + vhalf*64;
    const float* pp = g_proj + (size_t)b * Tt * PSTR;
    float* op = g_o + (size_t)b * Tt * Dd + h*DVv + vhalf*64 + vi;

    // loader decomposition of flat float4 index f = i*256 + tid (i=0..3):
    //   q4 = f & 15 (float4 within 64-float segment), s = (f>>4)&3, r = f>>6
    int lq4[4], ls[4], lr[4];
    const float* lsrc[4];
    #pragma unroll
    for (int i = 0; i < 4; i++) {
        int f = i * 256 + tid;
        lq4[i] = f & 15; ls[i] = (f >> 4) & 3; lr[i] = f >> 6;
    }
    #pragma unroll
    for (int i = 0; i < 4; i++) {
        switch (ls[i]) {
            case 0: lsrc[i] = pp + (size_t)lr[i]*PSTR + 192 + h*64 + lq4[i]*4; break;
            case 1: lsrc[i] = pp + (size_t)lr[i]*PSTR + 64 + lq4[i]*4; break;
            case 2: lsrc[i] = qp + (size_t)lr[i]*Cc + lq4[i]*4; break;
            default: lsrc[i] = vp + (size_t)lr[i]*DVv + lq4[i]*4; break;
        }
    }
    // per-chunk advance (floats) for each source
    size_t ladv[4];
    #pragma unroll
    for (int i = 0; i < 4; i++) {
        switch (ls[i]) {
            case 0: case 1: ladv[i] = (size_t)CH * PSTR; break;
            case 2:         ladv[i] = (size_t)CH * Cc;   break;
            default:        ladv[i] = (size_t)CH * DVv;  break;
        }
    }
    int ldst[4];
    #pragma unroll
    for (int i = 0; i < 4; i++) ldst[i] = (lr[i]*4 + ls[i])*64 + lq4[i]*4;

    __shared__ float sh[2][CH*256];
    float S[16];
    #pragma unroll
    for (int i = 0; i < 16; i++) S[i] = 0.f;

    // chunk 0 -> sh[0]
    #pragma unroll
    for (int i = 0; i < 4; i++)
        *(float4*)&sh[0][ldst[i]] = *(const float4*)lsrc[i];
    __syncthreads();

    int buf = 0;
    for (int c = 0; c < Tt/CH; c++) {
        // prefetch chunk c+1 into registers
        float4 pf[4];
        bool more = (c + 1) < (Tt/CH);
        if (more) {
            #pragma unroll
            for (int i = 0; i < 4; i++)
                pf[i] = *(const float4*)(lsrc[i] + (size_t)(c+1)*ladv[i]);
        }
        // compute CH steps from sh[buf]
        const float* cb = sh[buf];
        #pragma unroll 4
        for (int r = 0; r < CH; r++) {
            const float* base = cb + r*256;
            float vt = base[192 + vi];
            float acc = 0.f;
            #pragma unroll
            for (int j = 0; j < 4; j++) {
                float4 a4 = *(const float4*)(base +       cg*16 + 4*j);
                float4 k4 = *(const float4*)(base +  64 + cg*16 + 4*j);
                float4 q4 = *(const float4*)(base + 128 + cg*16 + 4*j);
                S[4*j+0] = fmaf(a4.x, S[4*j+0], k4.x*vt); acc = fmaf(q4.x, S[4*j+0], acc);
                S[4*j+1] = fmaf(a4.y, S[4*j+1], k4.y*vt); acc = fmaf(q4.y, S[4*j+1], acc);
                S[4*j+2] = fmaf(a4.z, S[4*j+2], k4.z*vt); acc = fmaf(q4.z, S[4*j+2], acc);
                S[4*j+3] = fmaf(a4.w, S[4*j+3], k4.w*vt); acc = fmaf(q4.w, S[4*j+3], acc);
            }
            acc += __shfl_xor_sync(0xffffffffu, acc, 1);
            acc += __shfl_xor_sync(0xffffffffu, acc, 2);
            if (cg == 0) op[(size_t)(c*CH + r) * Dd] = acc;
        }
        if (more) {
            int nb = buf ^ 1;
            #pragma unroll
            for (int i = 0; i < 4; i++)
                *(float4*)&sh[nb][ldst[i]] = pf[i];
            __syncthreads();
            buf = nb;
        }
    }
}

// ---------------- launch ---------------------------------------------------
extern "C" void kernel_launch(void* const* d_in, const int* in_sizes, int n_in,
                              void* d_out, int out_size)
{
    const float* x     = (const float*)d_in[0];
    const float* Wq    = (const float*)d_in[1];
    const float* Wk    = (const float*)d_in[2];
    const float* Wv    = (const float*)d_in[3];
    const float* Qc    = (const float*)d_in[4];
    const float* Vc    = (const float*)d_in[5];
    const float* Wa_w  = (const float*)d_in[6];
    const float* Wa_b  = (const float*)d_in[7];
    const float* Wo    = (const float*)d_in[8];
    const float* gamma = (const float*)d_in[9];
    const float* beta  = (const float*)d_in[10];
    float* out = (float*)d_out;

    float *xn, *wall, *proj, *o;
    cudaGetSymbolAddress((void**)&xn,   g_xn);
    cudaGetSymbolAddress((void**)&wall, g_wall);
    cudaGetSymbolAddress((void**)&proj, g_proj);
    cudaGetSymbolAddress((void**)&o,    g_o);

    // 1. layernorm
    ln_kernel<<<Mm, 256>>>(x, gamma, beta);
    // 2. concat projection weights
    build_wall<<<(PSTR*Dd)/256, 256>>>(Wq, Wk, Wv, Wa_w);
    // 3. projection GEMM split into two half-grids (slot 4 = second half, for ncu)
    gemm_tf32<<<dim3(PSTR/128, Mm/256), 256>>>(PSTR, Dd, xn, wall, proj, nullptr);
    {
        // second half: rows 8192..16383
        const float* xn2 = xn + (size_t)(Mm/2)*Dd;
        float* proj2 = proj + (size_t)(Mm/2)*PSTR;
        gemm_tf32<<<dim3(PSTR/128, Mm/256), 256>>>(PSTR, Dd, xn2, wall, proj2, nullptr);
    }
    // 4. normalize k, sigmoid alpha
    epi_kernel<<<Mm, 128>>>(Wa_b);
    // 5. per-head q rotation + v up-projection
    head_kernel<<<dim3(Mm/64, Hh), 256>>>(Qc, Vc);
    // 6. recurrent scan (chunked)
    scan_kernel<<<128, 256>>>();
    // 7. output GEMM + residual
    gemm_tf32<<<dim3(Dd/128, Mm/128), 256>>>(Dd, Dd, o, Wo, out, x);
}

// round 6
// speedup vs baseline: 2.8396x; 1.2405x over previous
#include <cuda_runtime.h>
#include <cstdint>
#include <math.h>

// Problem constants
#define Bb   8
#define Tt   2048
#define Dd   1024
#define Hh   8
#define Cc   64
#define DVv  128
#define Mm   (Bb*Tt)        // 16384 token rows
#define PSTR  768           // padded projection stride
#define CH   16             // scan chunk

// ---------------- scratch -------------------------------------------------
__device__ float g_xn  [(size_t)Mm*Dd];
__device__ float g_wall[(size_t)PSTR*Dd];
__device__ float g_hwq [(size_t)512*Cc];      // concat Qc: row (h*64+e), col c
__device__ float g_hwv [(size_t)1024*Cc];     // concat Vc: row (h*128+d), col c
__device__ float g_proj[(size_t)Mm*PSTR];     // qlat|kn|vlat|alpha
__device__ float g_q   [(size_t)Mm*512];      // rotated q: [m][h*64+e]
__device__ float g_v   [(size_t)Mm*1024];     // up-proj v: [m][h*128+d]
__device__ float g_o   [(size_t)Mm*Dd];

// ---------------- 1. LayerNorm -------------------------------------------
__global__ __launch_bounds__(256)
void ln_kernel(const float* __restrict__ x, const float* __restrict__ gamma,
               const float* __restrict__ beta)
{
    int row = blockIdx.x;
    int tid = threadIdx.x;
    const float4* xr = (const float4*)(x + (size_t)row*Dd);
    float4 v = xr[tid];
    float s  = v.x + v.y + v.z + v.w;
    float s2 = v.x*v.x + v.y*v.y + v.z*v.z + v.w*v.w;
    #pragma unroll
    for (int o = 16; o > 0; o >>= 1) {
        s  += __shfl_xor_sync(0xffffffffu, s,  o);
        s2 += __shfl_xor_sync(0xffffffffu, s2, o);
    }
    __shared__ float r1[8], r2[8];
    int w = tid >> 5, l = tid & 31;
    if (l == 0) { r1[w] = s; r2[w] = s2; }
    __syncthreads();
    s = 0.f; s2 = 0.f;
    #pragma unroll
    for (int i = 0; i < 8; i++) { s += r1[i]; s2 += r2[i]; }
    float mu  = s * (1.f/Dd);
    float var = s2 * (1.f/Dd) - mu*mu;
    float inv = rsqrtf(var + 1e-5f);
    float4 g  = ((const float4*)gamma)[tid];
    float4 be = ((const float4*)beta)[tid];
    float4 o;
    o.x = (v.x - mu)*inv*g.x + be.x;
    o.y = (v.y - mu)*inv*g.y + be.y;
    o.z = (v.z - mu)*inv*g.z + be.z;
    o.w = (v.w - mu)*inv*g.w + be.w;
    ((float4*)(g_xn + (size_t)row*Dd))[tid] = o;
}

// ---------------- 2. weight prep: wall concat + head-weight concat --------
#define WALL_ELEMS (PSTR*Dd)
#define HWQ_ELEMS  (512*Cc)
#define HWV_ELEMS  (1024*Cc)
__global__ void prep_weights(const float* __restrict__ Wq, const float* __restrict__ Wk,
                             const float* __restrict__ Wv, const float* __restrict__ Wa,
                             const float* __restrict__ Qc, const float* __restrict__ Vc)
{
    int i = blockIdx.x * blockDim.x + threadIdx.x;
    if (i < WALL_ELEMS) {
        int row = i >> 10, col = i & 1023;
        float val;
        if      (row <  64) val = Wq[(size_t)row       *1024 + col];
        else if (row < 128) val = Wk[(size_t)(row- 64) *1024 + col];
        else if (row < 192) val = Wv[(size_t)(row-128) *1024 + col];
        else if (row < 704) val = Wa[(size_t)(row-192) *1024 + col];
        else                val = 0.f;
        g_wall[i] = val;
    } else if (i < WALL_ELEMS + HWQ_ELEMS) {
        int j = i - WALL_ELEMS;          // row n = h*64+e, col c
        int n = j >> 6, c = j & 63;
        int h = n >> 6, e = n & 63;
        g_hwq[j] = Qc[(size_t)h*Cc*Cc + (size_t)c*Cc + e];
    } else if (i < WALL_ELEMS + HWQ_ELEMS + HWV_ELEMS) {
        int j = i - WALL_ELEMS - HWQ_ELEMS;  // row n = h*128+d, col c
        int n = j >> 6, c = j & 63;
        int h = n >> 7, d = n & 127;
        g_hwv[j] = Vc[(size_t)h*Cc*DVv + (size_t)c*DVv + d];
    }
}

// ---------------- 3. TF32 tensor-core GEMM  Y[M,N] = A[M,K] @ W[N,K]^T ----
__device__ __forceinline__ uint32_t f2tf32(float f) {
    uint32_t u;
    asm volatile("cvt.rna.tf32.f32 %0, %1;" : "=r"(u) : "f"(f));
    return u;
}
__device__ __forceinline__ void mma_tf32(float c[4], const uint32_t a[4], const uint32_t b[2]) {
    asm volatile(
        "mma.sync.aligned.m16n8k8.row.col.f32.tf32.tf32.f32 "
        "{%0,%1,%2,%3}, {%4,%5,%6,%7}, {%8,%9}, {%0,%1,%2,%3};\n"
        : "+f"(c[0]), "+f"(c[1]), "+f"(c[2]), "+f"(c[3])
        : "r"(a[0]), "r"(a[1]), "r"(a[2]), "r"(a[3]), "r"(b[0]), "r"(b[1]));
}

__global__ __launch_bounds__(256, 2)
void gemm_tf32(int K, int lda, int ldy,
               const float* __restrict__ A,
               const float* __restrict__ W,
               float* __restrict__ Y,
               const float* __restrict__ resid)
{
    __shared__ uint32_t As[2][128*20];
    __shared__ uint32_t Bs[2][128*20];

    int tid  = threadIdx.x;
    int lane = tid & 31, warp = tid >> 5;
    int wm = warp & 1, wn = warp >> 1;
    int g  = lane >> 2, tig = lane & 3;
    int row0 = blockIdx.y * 128;
    int col0 = blockIdx.x * 128;

    int lrow = tid >> 2;
    int kc   = (tid & 3) * 4;
    const float* Ap = A + (size_t)(row0 + lrow) * lda + kc;
    const float* Bp = W + (size_t)(col0 + lrow) * K + kc;

    float acc[4][4][4];
    #pragma unroll
    for (int i = 0; i < 4; i++)
        #pragma unroll
        for (int j = 0; j < 4; j++)
            #pragma unroll
            for (int e = 0; e < 4; e++) acc[i][j][e] = 0.f;

    {
        float4 a0 = *(const float4*)(Ap);
        float4 a1 = *(const float4*)(Ap + (size_t)64*lda);
        float4 b0 = *(const float4*)(Bp);
        float4 b1 = *(const float4*)(Bp + (size_t)64*K);
        *(uint4*)&As[0][lrow*20 + kc]      = make_uint4(f2tf32(a0.x), f2tf32(a0.y), f2tf32(a0.z), f2tf32(a0.w));
        *(uint4*)&As[0][(lrow+64)*20 + kc] = make_uint4(f2tf32(a1.x), f2tf32(a1.y), f2tf32(a1.z), f2tf32(a1.w));
        *(uint4*)&Bs[0][lrow*20 + kc]      = make_uint4(f2tf32(b0.x), f2tf32(b0.y), f2tf32(b0.z), f2tf32(b0.w));
        *(uint4*)&Bs[0][(lrow+64)*20 + kc] = make_uint4(f2tf32(b1.x), f2tf32(b1.y), f2tf32(b1.z), f2tf32(b1.w));
    }
    __syncthreads();

    int buf = 0;
    for (int k0 = 0; k0 < K; k0 += 16) {
        float4 pa0, pa1, pb0, pb1;
        bool more = (k0 + 16) < K;
        if (more) {
            pa0 = *(const float4*)(Ap + k0 + 16);
            pa1 = *(const float4*)(Ap + (size_t)64*lda + k0 + 16);
            pb0 = *(const float4*)(Bp + k0 + 16);
            pb1 = *(const float4*)(Bp + (size_t)64*K + k0 + 16);
        }

        const uint32_t* Ab  = As[buf];
        const uint32_t* Bb_ = Bs[buf];
        #pragma unroll
        for (int ks = 0; ks < 16; ks += 8) {
            uint32_t af[4][4], bf[4][2];
            #pragma unroll
            for (int i = 0; i < 4; i++) {
                int base = (wm*64 + i*16 + g)*20 + ks + tig;
                af[i][0] = Ab[base];
                af[i][1] = Ab[base + 8*20];
                af[i][2] = Ab[base + 4];
                af[i][3] = Ab[base + 8*20 + 4];
            }
            #pragma unroll
            for (int j = 0; j < 4; j++) {
                int base = (wn*32 + j*8 + g)*20 + ks + tig;
                bf[j][0] = Bb_[base];
                bf[j][1] = Bb_[base + 4];
            }
            #pragma unroll
            for (int i = 0; i < 4; i++)
                #pragma unroll
                for (int j = 0; j < 4; j++)
                    mma_tf32(acc[i][j], af[i], bf[j]);
        }

        if (more) {
            int nb = buf ^ 1;
            *(uint4*)&As[nb][lrow*20 + kc]      = make_uint4(f2tf32(pa0.x), f2tf32(pa0.y), f2tf32(pa0.z), f2tf32(pa0.w));
            *(uint4*)&As[nb][(lrow+64)*20 + kc] = make_uint4(f2tf32(pa1.x), f2tf32(pa1.y), f2tf32(pa1.z), f2tf32(pa1.w));
            *(uint4*)&Bs[nb][lrow*20 + kc]      = make_uint4(f2tf32(pb0.x), f2tf32(pb0.y), f2tf32(pb0.z), f2tf32(pb0.w));
            *(uint4*)&Bs[nb][(lrow+64)*20 + kc] = make_uint4(f2tf32(pb1.x), f2tf32(pb1.y), f2tf32(pb1.z), f2tf32(pb1.w));
            __syncthreads();
            buf = nb;
        }
    }

    #pragma unroll
    for (int i = 0; i < 4; i++) {
        #pragma unroll
        for (int j = 0; j < 4; j++) {
            int m0 = row0 + wm*64 + i*16 + g;
            int n0 = col0 + wn*32 + j*8 + tig*2;
            #pragma unroll
            for (int half = 0; half < 2; half++) {
                int m = m0 + half*8;
                float2 val = make_float2(acc[i][j][half*2], acc[i][j][half*2+1]);
                if (resid) {
                    const float2 r = *(const float2*)(resid + (size_t)m*ldy + n0);
                    val.x += r.x; val.y += r.y;
                }
                *(float2*)(Y + (size_t)m*ldy + n0) = val;
            }
        }
    }
}

// ---------------- 4. epilogue: normalize k, sigmoid(alpha + bias) ---------
__global__ __launch_bounds__(128)
void epi_kernel(const float* __restrict__ Wa_b)
{
    int row = blockIdx.x;
    float* p = g_proj + (size_t)row * PSTR;
    int tid = threadIdx.x;
    float kv = 0.f, sq = 0.f;
    if (tid < 64) { kv = p[64 + tid]; sq = kv * kv; }
    #pragma unroll
    for (int o = 16; o > 0; o >>= 1) sq += __shfl_xor_sync(0xffffffffu, sq, o);
    __shared__ float part[2];
    if ((tid & 31) == 0 && tid < 64) part[tid >> 5] = sq;
    __syncthreads();
    float inv = 1.f / fmaxf(sqrtf(part[0] + part[1]), 1e-12f);
    if (tid < 64) p[64 + tid] = kv * inv;
    #pragma unroll
    for (int r = 0; r < 4; r++) {
        int j = tid + r * 128;
        float a = p[192 + j] + Wa_b[j];
        p[192 + j] = 1.f / (1.f + expf(-a));
    }
}

// ---------------- 5. recurrent scan (chunked, latency-hidden) --------------
// Per block: (b,h,vhalf). Stage CH steps of [a|k|q|v] (256 floats/step) into
// double-buffered smem; prefetch next chunk into regs during compute.
__global__ __launch_bounds__(256)
void scan_kernel()
{
    int blk   = blockIdx.x;
    int bh    = blk >> 1;
    int vhalf = blk & 1;
    int b = bh >> 3, h = bh & 7;
    int tid = threadIdx.x;
    int vi  = tid >> 2;
    int cg  = tid & 3;
    const float* qp = g_q + (size_t)(b*Tt)*512 + h*64;
    const float* vp = g_v + (size_t)(b*Tt)*1024 + h*128 + vhalf*64;
    const float* pp = g_proj + (size_t)b * Tt * PSTR;
    float* op = g_o + (size_t)b * Tt * Dd + h*DVv + vhalf*64 + vi;

    // loader: flat float4 index f = i*256 + tid; q4 = f&15, s = (f>>4)&3, r = f>>6
    int lq4[4], ls[4], lr[4];
    const float* lsrc[4];
    size_t ladv[4];
    int ldst[4];
    #pragma unroll
    for (int i = 0; i < 4; i++) {
        int f = i * 256 + tid;
        lq4[i] = f & 15; ls[i] = (f >> 4) & 3; lr[i] = f >> 6;
        switch (ls[i]) {
            case 0:  lsrc[i] = pp + (size_t)lr[i]*PSTR + 192 + h*64 + lq4[i]*4; ladv[i] = (size_t)CH*PSTR; break;
            case 1:  lsrc[i] = pp + (size_t)lr[i]*PSTR + 64 + lq4[i]*4;         ladv[i] = (size_t)CH*PSTR; break;
            case 2:  lsrc[i] = qp + (size_t)lr[i]*512 + lq4[i]*4;               ladv[i] = (size_t)CH*512;  break;
            default: lsrc[i] = vp + (size_t)lr[i]*1024 + lq4[i]*4;              ladv[i] = (size_t)CH*1024; break;
        }
        ldst[i] = (lr[i]*4 + ls[i])*64 + lq4[i]*4;
    }

    __shared__ float sh[2][CH*256];
    float S[16];
    #pragma unroll
    for (int i = 0; i < 16; i++) S[i] = 0.f;

    #pragma unroll
    for (int i = 0; i < 4; i++)
        *(float4*)&sh[0][ldst[i]] = *(const float4*)lsrc[i];
    __syncthreads();

    int buf = 0;
    for (int c = 0; c < Tt/CH; c++) {
        float4 pf[4];
        bool more = (c + 1) < (Tt/CH);
        if (more) {
            #pragma unroll
            for (int i = 0; i < 4; i++)
                pf[i] = *(const float4*)(lsrc[i] + (size_t)(c+1)*ladv[i]);
        }
        const float* cb = sh[buf];
        #pragma unroll 4
        for (int r = 0; r < CH; r++) {
            const float* base = cb + r*256;
            float vt = base[192 + vi];
            float acc = 0.f;
            #pragma unroll
            for (int j = 0; j < 4; j++) {
                float4 a4 = *(const float4*)(base +       cg*16 + 4*j);
                float4 k4 = *(const float4*)(base +  64 + cg*16 + 4*j);
                float4 q4 = *(const float4*)(base + 128 + cg*16 + 4*j);
                S[4*j+0] = fmaf(a4.x, S[4*j+0], k4.x*vt); acc = fmaf(q4.x, S[4*j+0], acc);
                S[4*j+1] = fmaf(a4.y, S[4*j+1], k4.y*vt); acc = fmaf(q4.y, S[4*j+1], acc);
                S[4*j+2] = fmaf(a4.z, S[4*j+2], k4.z*vt); acc = fmaf(q4.z, S[4*j+2], acc);
                S[4*j+3] = fmaf(a4.w, S[4*j+3], k4.w*vt); acc = fmaf(q4.w, S[4*j+3], acc);
            }
            acc += __shfl_xor_sync(0xffffffffu, acc, 1);
            acc += __shfl_xor_sync(0xffffffffu, acc, 2);
            if (cg == 0) op[(size_t)(c*CH + r) * Dd] = acc;
        }
        if (more) {
            int nb = buf ^ 1;
            #pragma unroll
            for (int i = 0; i < 4; i++)
                *(float4*)&sh[nb][ldst[i]] = pf[i];
            __syncthreads();
            buf = nb;
        }
    }
}

// ---------------- launch ---------------------------------------------------
extern "C" void kernel_launch(void* const* d_in, const int* in_sizes, int n_in,
                              void* d_out, int out_size)
{
    const float* x     = (const float*)d_in[0];
    const float* Wq    = (const float*)d_in[1];
    const float* Wk    = (const float*)d_in[2];
    const float* Wv    = (const float*)d_in[3];
    const float* Qc    = (const float*)d_in[4];
    const float* Vc    = (const float*)d_in[5];
    const float* Wa_w  = (const float*)d_in[6];
    const float* Wa_b  = (const float*)d_in[7];
    const float* Wo    = (const float*)d_in[8];
    const float* gamma = (const float*)d_in[9];
    const float* beta  = (const float*)d_in[10];
    float* out = (float*)d_out;

    float *xn, *wall, *hwq, *hwv, *proj, *q, *v, *o;
    cudaGetSymbolAddress((void**)&xn,   g_xn);
    cudaGetSymbolAddress((void**)&wall, g_wall);
    cudaGetSymbolAddress((void**)&hwq,  g_hwq);
    cudaGetSymbolAddress((void**)&hwv,  g_hwv);
    cudaGetSymbolAddress((void**)&proj, g_proj);
    cudaGetSymbolAddress((void**)&q,    g_q);
    cudaGetSymbolAddress((void**)&v,    g_v);
    cudaGetSymbolAddress((void**)&o,    g_o);

    int prep_total = WALL_ELEMS + HWQ_ELEMS + HWV_ELEMS;

    // 1. layernorm
    ln_kernel<<<Mm, 256>>>(x, gamma, beta);
    // 2. weight prep (wall concat + head-weight concat)
    prep_weights<<<(prep_total + 255)/256, 256>>>(Wq, Wk, Wv, Wa_w, Qc, Vc);
    // 3. projection GEMM: proj[16384,768] = xn @ wall^T (K=1024)
    gemm_tf32<<<dim3(PSTR/128, Mm/128), 256>>>(Dd, Dd, PSTR, xn, wall, proj, nullptr);
    // 4. normalize k, sigmoid alpha
    epi_kernel<<<Mm, 128>>>(Wa_b);
    // 5a. head Q GEMM: q[16384,512] = q_lat @ hwq^T (K=64, A stride 768)
    gemm_tf32<<<dim3(512/128, Mm/128), 256>>>(Cc, PSTR, 512, proj, hwq, q, nullptr);
    // 5b. head V GEMM: v[16384,1024] = v_lat @ hwv^T (K=64, A stride 768, A offset 128)
    gemm_tf32<<<dim3(1024/128, Mm/128), 256>>>(Cc, PSTR, 1024, proj + 128, hwv, v, nullptr);
    // 6. recurrent scan (chunked)
    scan_kernel<<<128, 256>>>();
    // 7. output GEMM + residual: out = o @ Wo^T + x (K=1024)
    gemm_tf32<<<dim3(Dd/128, Mm/128), 256>>>(Dd, Dd, Dd, o, Wo, out, x);
}

// round 7
// speedup vs baseline: 3.5232x; 1.2407x over previous
#include <cuda_runtime.h>
#include <cstdint>
#include <math.h>

// Problem constants
#define Bb   8
#define Tt   2048
#define Dd   1024
#define Hh   8
#define Cc   64
#define DVv  128
#define Mm   (Bb*Tt)
#define PSTR  768
#define CH   16

// ---------------- scratch -------------------------------------------------
__device__ float g_xn  [(size_t)Mm*Dd];
__device__ float g_wall[(size_t)PSTR*Dd];
__device__ float g_hwq [(size_t)512*Cc];
__device__ float g_hwv [(size_t)1024*Cc];
__device__ float g_proj[(size_t)Mm*PSTR];     // qlat|kn|vlat|alpha(sigmoided)
__device__ float g_q   [(size_t)Mm*512];
__device__ float g_v   [(size_t)Mm*1024];
__device__ float g_o   [(size_t)Mm*Dd];

// ---------------- 1. LayerNorm -------------------------------------------
__global__ __launch_bounds__(256)
void ln_kernel(const float* __restrict__ x, const float* __restrict__ gamma,
               const float* __restrict__ beta)
{
    int row = blockIdx.x;
    int tid = threadIdx.x;
    const float4* xr = (const float4*)(x + (size_t)row*Dd);
    float4 v = xr[tid];
    float s  = v.x + v.y + v.z + v.w;
    float s2 = v.x*v.x + v.y*v.y + v.z*v.z + v.w*v.w;
    #pragma unroll
    for (int o = 16; o > 0; o >>= 1) {
        s  += __shfl_xor_sync(0xffffffffu, s,  o);
        s2 += __shfl_xor_sync(0xffffffffu, s2, o);
    }
    __shared__ float r1[8], r2[8];
    int w = tid >> 5, l = tid & 31;
    if (l == 0) { r1[w] = s; r2[w] = s2; }
    __syncthreads();
    s = 0.f; s2 = 0.f;
    #pragma unroll
    for (int i = 0; i < 8; i++) { s += r1[i]; s2 += r2[i]; }
    float mu  = s * (1.f/Dd);
    float var = s2 * (1.f/Dd) - mu*mu;
    float inv = rsqrtf(var + 1e-5f);
    float4 g  = ((const float4*)gamma)[tid];
    float4 be = ((const float4*)beta)[tid];
    float4 o;
    o.x = (v.x - mu)*inv*g.x + be.x;
    o.y = (v.y - mu)*inv*g.y + be.y;
    o.z = (v.z - mu)*inv*g.z + be.z;
    o.w = (v.w - mu)*inv*g.w + be.w;
    ((float4*)(g_xn + (size_t)row*Dd))[tid] = o;
}

// ---------------- 2. weight prep ------------------------------------------
#define WALL_ELEMS (PSTR*Dd)
#define HWQ_ELEMS  (512*Cc)
#define HWV_ELEMS  (1024*Cc)
__global__ void prep_weights(const float* __restrict__ Wq, const float* __restrict__ Wk,
                             const float* __restrict__ Wv, const float* __restrict__ Wa,
                             const float* __restrict__ Qc, const float* __restrict__ Vc)
{
    int i = blockIdx.x * blockDim.x + threadIdx.x;
    if (i < WALL_ELEMS) {
        int row = i >> 10, col = i & 1023;
        float val;
        if      (row <  64) val = Wq[(size_t)row       *1024 + col];
        else if (row < 128) val = Wk[(size_t)(row- 64) *1024 + col];
        else if (row < 192) val = Wv[(size_t)(row-128) *1024 + col];
        else if (row < 704) val = Wa[(size_t)(row-192) *1024 + col];
        else                val = 0.f;
        g_wall[i] = val;
    } else if (i < WALL_ELEMS + HWQ_ELEMS) {
        int j = i - WALL_ELEMS;
        int n = j >> 6, c = j & 63;
        int h = n >> 6, e = n & 63;
        g_hwq[j] = Qc[(size_t)h*Cc*Cc + (size_t)c*Cc + e];
    } else if (i < WALL_ELEMS + HWQ_ELEMS + HWV_ELEMS) {
        int j = i - WALL_ELEMS - HWQ_ELEMS;
        int n = j >> 6, c = j & 63;
        int h = n >> 7, d = n & 127;
        g_hwv[j] = Vc[(size_t)h*Cc*DVv + (size_t)c*DVv + d];
    }
}

// ---------------- 3. TF32 GEMM, 64x64 warp tile ---------------------------
// Y[M,N] = A[M,K] @ W[N,K]^T. 128 threads, 2x2 warps of 64x64.
// mode 0: plain; 1: += resid; 2: proj epilogue (knorm cols 64-127, sigmoid 192-703)
__device__ __forceinline__ uint32_t f2tf32(float f) {
    uint32_t u;
    asm volatile("cvt.rna.tf32.f32 %0, %1;" : "=r"(u) : "f"(f));
    return u;
}
__device__ __forceinline__ void mma_tf32(float c[4], const uint32_t a[4], const uint32_t b[2]) {
    asm volatile(
        "mma.sync.aligned.m16n8k8.row.col.f32.tf32.tf32.f32 "
        "{%0,%1,%2,%3}, {%4,%5,%6,%7}, {%8,%9}, {%0,%1,%2,%3};\n"
        : "+f"(c[0]), "+f"(c[1]), "+f"(c[2]), "+f"(c[3])
        : "r"(a[0]), "r"(a[1]), "r"(a[2]), "r"(a[3]), "r"(b[0]), "r"(b[1]));
}

__global__ __launch_bounds__(128, 2)
void gemm_tf32(int K, int lda, int ldy, int mode,
               const float* __restrict__ A,
               const float* __restrict__ W,
               float* __restrict__ Y,
               const float* __restrict__ resid,
               const float* __restrict__ bias)
{
    __shared__ uint32_t As[2][128*20];
    __shared__ uint32_t Bs[2][128*20];

    int tid  = threadIdx.x;
    int lane = tid & 31, warp = tid >> 5;
    int wm = warp & 1, wn = warp >> 1;       // 2x2 warp grid
    int g  = lane >> 2, tig = lane & 3;
    int row0 = blockIdx.y * 128;
    int col0 = blockIdx.x * 128;

    // loader: 4 float4/thread: rows lrow, lrow+64; k halves kb, kb+4
    int lrow = tid >> 1;
    int kb   = (tid & 1) * 8;
    const float* Ap = A + (size_t)(row0 + lrow) * lda + kb;
    const float* Bp = W + (size_t)(col0 + lrow) * K + kb;

    float acc[4][8][4];
    #pragma unroll
    for (int i = 0; i < 4; i++)
        #pragma unroll
        for (int j = 0; j < 8; j++)
            #pragma unroll
            for (int e = 0; e < 4; e++) acc[i][j][e] = 0.f;

    // preload k0 = 0
    {
        float4 a00 = *(const float4*)(Ap);
        float4 a01 = *(const float4*)(Ap + 4);
        float4 a10 = *(const float4*)(Ap + (size_t)64*lda);
        float4 a11 = *(const float4*)(Ap + (size_t)64*lda + 4);
        float4 b00 = *(const float4*)(Bp);
        float4 b01 = *(const float4*)(Bp + 4);
        float4 b10 = *(const float4*)(Bp + (size_t)64*K);
        float4 b11 = *(const float4*)(Bp + (size_t)64*K + 4);
        *(uint4*)&As[0][lrow*20 + kb]          = make_uint4(f2tf32(a00.x), f2tf32(a00.y), f2tf32(a00.z), f2tf32(a00.w));
        *(uint4*)&As[0][lrow*20 + kb + 4]      = make_uint4(f2tf32(a01.x), f2tf32(a01.y), f2tf32(a01.z), f2tf32(a01.w));
        *(uint4*)&As[0][(lrow+64)*20 + kb]     = make_uint4(f2tf32(a10.x), f2tf32(a10.y), f2tf32(a10.z), f2tf32(a10.w));
        *(uint4*)&As[0][(lrow+64)*20 + kb + 4] = make_uint4(f2tf32(a11.x), f2tf32(a11.y), f2tf32(a11.z), f2tf32(a11.w));
        *(uint4*)&Bs[0][lrow*20 + kb]          = make_uint4(f2tf32(b00.x), f2tf32(b00.y), f2tf32(b00.z), f2tf32(b00.w));
        *(uint4*)&Bs[0][lrow*20 + kb + 4]      = make_uint4(f2tf32(b01.x), f2tf32(b01.y), f2tf32(b01.z), f2tf32(b01.w));
        *(uint4*)&Bs[0][(lrow+64)*20 + kb]     = make_uint4(f2tf32(b10.x), f2tf32(b10.y), f2tf32(b10.z), f2tf32(b10.w));
        *(uint4*)&Bs[0][(lrow+64)*20 + kb + 4] = make_uint4(f2tf32(b11.x), f2tf32(b11.y), f2tf32(b11.z), f2tf32(b11.w));
    }
    __syncthreads();

    int buf = 0;
    for (int k0 = 0; k0 < K; k0 += 16) {
        float4 pa00, pa01, pa10, pa11, pb00, pb01, pb10, pb11;
        bool more = (k0 + 16) < K;
        if (more) {
            const float* Ak = Ap + k0 + 16;
            const float* Bk = Bp + k0 + 16;
            pa00 = *(const float4*)(Ak);
            pa01 = *(const float4*)(Ak + 4);
            pa10 = *(const float4*)(Ak + (size_t)64*lda);
            pa11 = *(const float4*)(Ak + (size_t)64*lda + 4);
            pb00 = *(const float4*)(Bk);
            pb01 = *(const float4*)(Bk + 4);
            pb10 = *(const float4*)(Bk + (size_t)64*K);
            pb11 = *(const float4*)(Bk + (size_t)64*K + 4);
        }

        const uint32_t* Ab  = As[buf];
        const uint32_t* Bb_ = Bs[buf];
        #pragma unroll
        for (int ks = 0; ks < 16; ks += 8) {
            uint32_t af[4][4], bf[8][2];
            #pragma unroll
            for (int i = 0; i < 4; i++) {
                int base = (wm*64 + i*16 + g)*20 + ks + tig;
                af[i][0] = Ab[base];
                af[i][1] = Ab[base + 8*20];
                af[i][2] = Ab[base + 4];
                af[i][3] = Ab[base + 8*20 + 4];
            }
            #pragma unroll
            for (int j = 0; j < 8; j++) {
                int base = (wn*64 + j*8 + g)*20 + ks + tig;
                bf[j][0] = Bb_[base];
                bf[j][1] = Bb_[base + 4];
            }
            #pragma unroll
            for (int i = 0; i < 4; i++)
                #pragma unroll
                for (int j = 0; j < 8; j++)
                    mma_tf32(acc[i][j], af[i], bf[j]);
        }

        if (more) {
            int nb = buf ^ 1;
            *(uint4*)&As[nb][lrow*20 + kb]          = make_uint4(f2tf32(pa00.x), f2tf32(pa00.y), f2tf32(pa00.z), f2tf32(pa00.w));
            *(uint4*)&As[nb][lrow*20 + kb + 4]      = make_uint4(f2tf32(pa01.x), f2tf32(pa01.y), f2tf32(pa01.z), f2tf32(pa01.w));
            *(uint4*)&As[nb][(lrow+64)*20 + kb]     = make_uint4(f2tf32(pa10.x), f2tf32(pa10.y), f2tf32(pa10.z), f2tf32(pa10.w));
            *(uint4*)&As[nb][(lrow+64)*20 + kb + 4] = make_uint4(f2tf32(pa11.x), f2tf32(pa11.y), f2tf32(pa11.z), f2tf32(pa11.w));
            *(uint4*)&Bs[nb][lrow*20 + kb]          = make_uint4(f2tf32(pb00.x), f2tf32(pb00.y), f2tf32(pb00.z), f2tf32(pb00.w));
            *(uint4*)&Bs[nb][lrow*20 + kb + 4]      = make_uint4(f2tf32(pb01.x), f2tf32(pb01.y), f2tf32(pb01.z), f2tf32(pb01.w));
            *(uint4*)&Bs[nb][(lrow+64)*20 + kb]     = make_uint4(f2tf32(pb10.x), f2tf32(pb10.y), f2tf32(pb10.z), f2tf32(pb10.w));
            *(uint4*)&Bs[nb][(lrow+64)*20 + kb + 4] = make_uint4(f2tf32(pb11.x), f2tf32(pb11.y), f2tf32(pb11.z), f2tf32(pb11.w));
            __syncthreads();
            buf = nb;
        }
    }

    // epilogue
    bool knorm_warp = (mode == 2) && (col0 + wn*64 == 64);
    #pragma unroll
    for (int i = 0; i < 4; i++) {
        #pragma unroll
        for (int half = 0; half < 2; half++) {
            int m = row0 + wm*64 + i*16 + g + half*8;
            float scale = 1.f;
            if (knorm_warp) {
                float s = 0.f;
                #pragma unroll
                for (int j = 0; j < 8; j++) {
                    float e0 = acc[i][j][half*2], e1 = acc[i][j][half*2+1];
                    s = fmaf(e0, e0, s); s = fmaf(e1, e1, s);
                }
                s += __shfl_xor_sync(0xffffffffu, s, 1);
                s += __shfl_xor_sync(0xffffffffu, s, 2);
                scale = 1.f / fmaxf(sqrtf(s), 1e-12f);
            }
            #pragma unroll
            for (int j = 0; j < 8; j++) {
                int n0 = col0 + wn*64 + j*8 + tig*2;
                float2 val = make_float2(acc[i][j][half*2], acc[i][j][half*2+1]);
                if (mode == 1) {
                    const float2 r = *(const float2*)(resid + (size_t)m*ldy + n0);
                    val.x += r.x; val.y += r.y;
                } else if (mode == 2) {
                    if (knorm_warp) {
                        val.x *= scale; val.y *= scale;
                    } else if (n0 >= 192 && n0 < 704) {
                        float2 bb = *(const float2*)(bias + n0 - 192);
                        val.x = 1.f / (1.f + expf(-(val.x + bb.x)));
                        val.y = 1.f / (1.f + expf(-(val.y + bb.y)));
                    }
                }
                *(float2*)(Y + (size_t)m*ldy + n0) = val;
            }
        }
    }
}

// ---------------- 4. recurrent scan (8c x 2v tiles, chunked) ---------------
// Block = (b,h,vhalf). 256 threads: vg = tid>>3 (32 v-pairs), cg = tid&7 (8 c's).
// Per step: 6 LDS.128 + 1 LDS.64, 48 FMA, 6 SHFL; FMA-bound.
__global__ __launch_bounds__(256)
void scan_kernel()
{
    int blk   = blockIdx.x;
    int bh    = blk >> 1;
    int vhalf = blk & 1;
    int b = bh >> 3, h = bh & 7;
    int tid = threadIdx.x;
    int vg  = tid >> 3;      // 0..31
    int cg  = tid & 7;       // 0..7
    const float* qp = g_q + (size_t)(b*Tt)*512 + h*64;
    const float* vp = g_v + (size_t)(b*Tt)*1024 + h*128 + vhalf*64;
    const float* pp = g_proj + (size_t)b * Tt * PSTR;
    float* op = g_o + (size_t)b * Tt * Dd + h*DVv + vhalf*64 + vg*2;

    // chunk loader: flat float4 index f = i*256 + tid; q4=f&15, s=(f>>4)&3, r=f>>6
    const float* lsrc[4];
    size_t ladv[4];
    int ldst[4];
    #pragma unroll
    for (int i = 0; i < 4; i++) {
        int f = i * 256 + tid;
        int lq4 = f & 15, ls = (f >> 4) & 3, lr = f >> 6;
        switch (ls) {
            case 0:  lsrc[i] = pp + (size_t)lr*PSTR + 192 + h*64 + lq4*4; ladv[i] = (size_t)CH*PSTR; break;
            case 1:  lsrc[i] = pp + (size_t)lr*PSTR + 64 + lq4*4;         ladv[i] = (size_t)CH*PSTR; break;
            case 2:  lsrc[i] = qp + (size_t)lr*512 + lq4*4;               ladv[i] = (size_t)CH*512;  break;
            default: lsrc[i] = vp + (size_t)lr*1024 + lq4*4;              ladv[i] = (size_t)CH*1024; break;
        }
        ldst[i] = (lr*4 + ls)*64 + lq4*4;
    }

    __shared__ float sh[2][CH*256];
    float S0[8], S1[8];
    #pragma unroll
    for (int i = 0; i < 8; i++) { S0[i] = 0.f; S1[i] = 0.f; }

    #pragma unroll
    for (int i = 0; i < 4; i++)
        *(float4*)&sh[0][ldst[i]] = *(const float4*)lsrc[i];
    __syncthreads();

    int buf = 0;
    for (int c = 0; c < Tt/CH; c++) {
        float4 pf[4];
        bool more = (c + 1) < (Tt/CH);
        if (more) {
            #pragma unroll
            for (int i = 0; i < 4; i++)
                pf[i] = *(const float4*)(lsrc[i] + (size_t)(c+1)*ladv[i]);
        }
        const float* cb = sh[buf];
        #pragma unroll 4
        for (int r = 0; r < CH; r++) {
            const float* base = cb + r*256;
            float4 a0 = *(const float4*)(base +       cg*8);
            float4 a1 = *(const float4*)(base +       cg*8 + 4);
            float4 k0 = *(const float4*)(base +  64 + cg*8);
            float4 k1 = *(const float4*)(base +  64 + cg*8 + 4);
            float4 q0 = *(const float4*)(base + 128 + cg*8);
            float4 q1 = *(const float4*)(base + 128 + cg*8 + 4);
            float2 vt = *(const float2*)(base + 192 + vg*2);
            float acc0 = 0.f, acc1 = 0.f;

            S0[0] = fmaf(a0.x, S0[0], k0.x*vt.x); acc0 = fmaf(q0.x, S0[0], acc0);
            S1[0] = fmaf(a0.x, S1[0], k0.x*vt.y); acc1 = fmaf(q0.x, S1[0], acc1);
            S0[1] = fmaf(a0.y, S0[1], k0.y*vt.x); acc0 = fmaf(q0.y, S0[1], acc0);
            S1[1] = fmaf(a0.y, S1[1], k0.y*vt.y); acc1 = fmaf(q0.y, S1[1], acc1);
            S0[2] = fmaf(a0.z, S0[2], k0.z*vt.x); acc0 = fmaf(q0.z, S0[2], acc0);
            S1[2] = fmaf(a0.z, S1[2], k0.z*vt.y); acc1 = fmaf(q0.z, S1[2], acc1);
            S0[3] = fmaf(a0.w, S0[3], k0.w*vt.x); acc0 = fmaf(q0.w, S0[3], acc0);
            S1[3] = fmaf(a0.w, S1[3], k0.w*vt.y); acc1 = fmaf(q0.w, S1[3], acc1);
            S0[4] = fmaf(a1.x, S0[4], k1.x*vt.x); acc0 = fmaf(q1.x, S0[4], acc0);
            S1[4] = fmaf(a1.x, S1[4], k1.x*vt.y); acc1 = fmaf(q1.x, S1[4], acc1);
            S0[5] = fmaf(a1.y, S0[5], k1.y*vt.x); acc0 = fmaf(q1.y, S0[5], acc0);
            S1[5] = fmaf(a1.y, S1[5], k1.y*vt.y); acc1 = fmaf(q1.y, S1[5], acc1);
            S0[6] = fmaf(a1.z, S0[6], k1.z*vt.x); acc0 = fmaf(q1.z, S0[6], acc0);
            S1[6] = fmaf(a1.z, S1[6], k1.z*vt.y); acc1 = fmaf(q1.z, S1[6], acc1);
            S0[7] = fmaf(a1.w, S0[7], k1.w*vt.x); acc0 = fmaf(q1.w, S0[7], acc0);
            S1[7] = fmaf(a1.w, S1[7], k1.w*vt.y); acc1 = fmaf(q1.w, S1[7], acc1);

            acc0 += __shfl_xor_sync(0xffffffffu, acc0, 1);
            acc1 += __shfl_xor_sync(0xffffffffu, acc1, 1);
            acc0 += __shfl_xor_sync(0xffffffffu, acc0, 2);
            acc1 += __shfl_xor_sync(0xffffffffu, acc1, 2);
            acc0 += __shfl_xor_sync(0xffffffffu, acc0, 4);
            acc1 += __shfl_xor_sync(0xffffffffu, acc1, 4);
            if (cg == 0)
                *(float2*)(op + (size_t)(c*CH + r) * Dd) = make_float2(acc0, acc1);
        }
        if (more) {
            int nb = buf ^ 1;
            #pragma unroll
            for (int i = 0; i < 4; i++)
                *(float4*)&sh[nb][ldst[i]] = pf[i];
            __syncthreads();
            buf = nb;
        }
    }
}

// ---------------- launch ---------------------------------------------------
extern "C" void kernel_launch(void* const* d_in, const int* in_sizes, int n_in,
                              void* d_out, int out_size)
{
    const float* x     = (const float*)d_in[0];
    const float* Wq    = (const float*)d_in[1];
    const float* Wk    = (const float*)d_in[2];
    const float* Wv    = (const float*)d_in[3];
    const float* Qc    = (const float*)d_in[4];
    const float* Vc    = (const float*)d_in[5];
    const float* Wa_w  = (const float*)d_in[6];
    const float* Wa_b  = (const float*)d_in[7];
    const float* Wo    = (const float*)d_in[8];
    const float* gamma = (const float*)d_in[9];
    const float* beta  = (const float*)d_in[10];
    float* out = (float*)d_out;

    float *xn, *wall, *hwq, *hwv, *proj, *q, *v, *o;
    cudaGetSymbolAddress((void**)&xn,   g_xn);
    cudaGetSymbolAddress((void**)&wall, g_wall);
    cudaGetSymbolAddress((void**)&hwq,  g_hwq);
    cudaGetSymbolAddress((void**)&hwv,  g_hwv);
    cudaGetSymbolAddress((void**)&proj, g_proj);
    cudaGetSymbolAddress((void**)&q,    g_q);
    cudaGetSymbolAddress((void**)&v,    g_v);
    cudaGetSymbolAddress((void**)&o,    g_o);

    int prep_total = WALL_ELEMS + HWQ_ELEMS + HWV_ELEMS;

    // 1. layernorm
    ln_kernel<<<Mm, 256>>>(x, gamma, beta);
    // 2. weight prep
    prep_weights<<<(prep_total + 255)/256, 256>>>(Wq, Wk, Wv, Wa_w, Qc, Vc);
    // 3. projection GEMM + fused epi (knorm + sigmoid): proj = xn @ wall^T
    gemm_tf32<<<dim3(PSTR/128, Mm/128), 128>>>(Dd, Dd, PSTR, 2, xn, wall, proj, nullptr, Wa_b);
    // 4. head Q GEMM: q[16384,512] = q_lat @ hwq^T (K=64)
    gemm_tf32<<<dim3(512/128, Mm/128), 128>>>(Cc, PSTR, 512, 0, proj, hwq, q, nullptr, nullptr);
    // 5. head V GEMM: v[16384,1024] = v_lat @ hwv^T (K=64)
    gemm_tf32<<<dim3(1024/128, Mm/128), 128>>>(Cc, PSTR, 1024, 0, proj + 128, hwv, v, nullptr, nullptr);
    // 6. recurrent scan
    scan_kernel<<<128, 256>>>();
    // 7. output GEMM + residual: out = o @ Wo^T + x
    gemm_tf32<<<dim3(Dd/128, Mm/128), 128>>>(Dd, Dd, Dd, 1, o, Wo, out, x, nullptr);
}